// round 10
// baseline (speedup 1.0000x reference)
#include <cuda_runtime.h>
#include <cuda_bf16.h>

#define BB   16
#define CC   192
#define TXN  1024
#define MAXY 4096

// Single fused kernel. One block per (b,c) row, 256 threads.
// Each block independently: loads logw row (L2-broadcast), computes
// w=ceil(exp(logw)) masked by x_len, block-scans durations, scatters the
// token-id map into SMEM (int16), stages m / exp(logs) rows into SMEM,
// then streams: z = idx>=0 ? m[idx] + noise*e[idx] : noise.
// No global idx map -> no cross-kernel dependency, ~48MB less L2 traffic.
__global__ void __launch_bounds__(256)
fused_kernel(const float* __restrict__ m_p,
             const float* __restrict__ logs_p,
             const float* __restrict__ logw,
             const int* __restrict__ x_lengths,
             const float* __restrict__ noise,
             float* __restrict__ z,
             float* __restrict__ y_mask_out) {
    __shared__ float sm[TXN];          // m row
    __shared__ float se[TXN];          // exp(logs) row
    __shared__ short sidx[MAXY];       // token id per frame, -1 = none (8KB)
    __shared__ int   warp_sums[8];
    __shared__ int   s_total;

    const int bc   = blockIdx.x;       // 0..BB*CC-1
    const int b    = bc / CC;
    const int tid  = threadIdx.x;
    const int lane = tid & 31;
    const int wid  = tid >> 5;

    const float4* __restrict__ nz4 = reinterpret_cast<const float4*>(noise) + (size_t)bc * (MAXY / 4);
    float4*       __restrict__ z4  = reinterpret_cast<float4*>(z)           + (size_t)bc * (MAXY / 4);

    // ---- issue all independent global loads up front ----
    float4 n[4];
    #pragma unroll
    for (int j = 0; j < 4; j++) n[j] = __ldcs(&nz4[tid + j * 256]);

    float4 mv = reinterpret_cast<const float4*>(m_p    + (size_t)bc * TXN)[tid];
    float4 sv = reinterpret_cast<const float4*>(logs_p + (size_t)bc * TXN)[tid];
    float4 lw = reinterpret_cast<const float4*>(logw   + (size_t)b  * TXN)[tid];
    const int xlen = max(x_lengths[b], 1);

    // ---- durations: w = ceil(exp(logw)) for t < xlen (accurate expf:
    //      result feeds ceil, ulp flips at integer boundaries matter) ----
    const int t0 = tid * 4;
    int w0 = (t0 + 0 < xlen) ? (int)ceilf(expf(lw.x)) : 0;
    int w1 = (t0 + 1 < xlen) ? (int)ceilf(expf(lw.y)) : 0;
    int w2 = (t0 + 2 < xlen) ? (int)ceilf(expf(lw.z)) : 0;
    int w3 = (t0 + 3 < xlen) ? (int)ceilf(expf(lw.w)) : 0;
    int tsum = w0 + w1 + w2 + w3;

    // block exclusive scan of per-thread sums (256 lanes)
    int c = tsum;
    #pragma unroll
    for (int o = 1; o < 32; o <<= 1) {
        int v = __shfl_up_sync(0xffffffffu, c, o);
        if (lane >= o) c += v;
    }
    if (lane == 31) warp_sums[wid] = c;
    __syncthreads();
    if (wid == 0 && lane < 8) {
        int v = warp_sums[lane];
        #pragma unroll
        for (int o = 1; o < 8; o <<= 1) {
            int u = __shfl_up_sync(0xffu, v, o);
            if (lane >= o) v += u;
        }
        warp_sums[lane] = v;
        if (lane == 7) s_total = v;
    }
    __syncthreads();

    const int wbase = (wid > 0) ? warp_sums[wid - 1] : 0;
    const int ebase = wbase + c - tsum;          // exclusive prefix for this thread
    const int total = s_total;

    // stage m and pre-exponentiated logs (MUFU off the hot chain)
    reinterpret_cast<float4*>(sm)[tid] = mv;
    {
        float4 e;
        e.x = __expf(sv.x); e.y = __expf(sv.y);
        e.z = __expf(sv.z); e.w = __expf(sv.w);
        reinterpret_cast<float4*>(se)[tid] = e;
    }

    // scatter token bands into smem idx map
    {
        int cum = ebase;
        int wv[4] = {w0, w1, w2, w3};
        #pragma unroll
        for (int k = 0; k < 4; k++) {
            const int start = cum;
            cum += wv[k];
            const int end = min(cum, MAXY);
            const short tok = (short)(t0 + k);
            for (int ty = start; ty < end; ty++) sidx[ty] = tok;
        }
    }
    // tail: frames beyond total have no token
    for (int ty = min(total, MAXY) + tid; ty < MAXY; ty += 256) sidx[ty] = -1;
    __syncthreads();

    // ---- stream: LDS (broadcast-friendly) + FFMA + streamed store ----
    #pragma unroll
    for (int j = 0; j < 4; j++) {
        const int v = (tid + j * 256) * 4;
        const float nv[4] = {n[j].x, n[j].y, n[j].z, n[j].w};
        float ov[4];
        #pragma unroll
        for (int k = 0; k < 4; k++) {
            const int t = sidx[v + k];
            ov[k] = (t >= 0) ? fmaf(nv[k], se[t], sm[t]) : nv[k];
        }
        __stcs(&z4[tid + j * 256], make_float4(ov[0], ov[1], ov[2], ov[3]));
    }

    // ---- y_mask: one block per batch writes ALL 4096 entries (4 per thread) ----
    if (y_mask_out != nullptr && (bc % CC) == 0) {
        const int ylen = min(max(total, 1), MAXY);
        float4* ym4 = reinterpret_cast<float4*>(y_mask_out + (size_t)b * MAXY);
        #pragma unroll
        for (int j = 0; j < 4; j++) {
            const int vi = tid + j * 256;       // float4 index, 0..1023
            const int v0 = vi * 4;
            float4 m;
            m.x = (v0 + 0 < ylen) ? 1.0f : 0.0f;
            m.y = (v0 + 1 < ylen) ? 1.0f : 0.0f;
            m.z = (v0 + 2 < ylen) ? 1.0f : 0.0f;
            m.w = (v0 + 3 < ylen) ? 1.0f : 0.0f;
            ym4[vi] = m;
        }
    }
}

extern "C" void kernel_launch(void* const* d_in, const int* in_sizes, int n_in,
                              void* d_out, int out_size) {
    const float* m_p    = (const float*)d_in[0];
    const float* logs_p = (const float*)d_in[1];
    const float* logw   = (const float*)d_in[2];
    const float* noise  = (const float*)d_in[3];
    const int*   xlens  = (const int*)d_in[4];

    float* out = (float*)d_out;
    const int zsize = BB * CC * MAXY;            // 12,582,912
    float* z = out;
    float* y_mask = (out_size >= zsize + BB * MAXY) ? (out + zsize) : nullptr;

    fused_kernel<<<BB * CC, 256>>>(m_p, logs_p, logw, xlens, noise, z, y_mask);
}

// round 11
// speedup vs baseline: 1.4443x; 1.4443x over previous
#include <cuda_runtime.h>
#include <cuda_bf16.h>

#define BB   16
#define CC   192
#define TXN  1024
#define MAXY 4096

// Scratch: token index per output frame (int16, -1 = no token -> z = noise)
__device__ short g_sidx[BB * MAXY];

// One block per batch, 1024 threads.
// PDL trigger fires AFTER g_sidx is fully written (y_mask, which expand never
// reads, is written after the trigger).
__global__ void build_map_kernel(const float* __restrict__ logw,
                                 const int* __restrict__ x_lengths,
                                 float* __restrict__ y_mask_out) {
    __shared__ int warp_sums[32];
    const int b    = blockIdx.x;
    const int t    = threadIdx.x;
    const int lane = t & 31;
    const int wid  = t >> 5;

    const int xlen = max(x_lengths[b], 1);
    int w = 0;
    if (t < xlen) {
        // accurate expf: feeds ceil(), ulp flips at integer boundaries matter
        w = (int)ceilf(expf(logw[b * TXN + t]));
    }

    // warp-level inclusive scan
    int c = w;
    #pragma unroll
    for (int o = 1; o < 32; o <<= 1) {
        int v = __shfl_up_sync(0xffffffffu, c, o);
        if (lane >= o) c += v;
    }
    if (lane == 31) warp_sums[wid] = c;
    __syncthreads();
    if (wid == 0) {
        int v = warp_sums[lane];
        #pragma unroll
        for (int o = 1; o < 32; o <<= 1) {
            int u = __shfl_up_sync(0xffffffffu, v, o);
            if (lane >= o) v += u;
        }
        warp_sums[lane] = v;
    }
    __syncthreads();

    const int base  = (wid > 0) ? warp_sums[wid - 1] : 0;
    const int cum   = base + c;               // inclusive prefix sum
    const int total = warp_sums[31];
    const int ylen  = min(max(total, 1), MAXY);

    short* __restrict__ row = g_sidx + b * MAXY;

    // band scatter: frames [cum-w, cum) belong to token t
    const int end = min(cum, MAXY);
    const short tok = (short)t;
    for (int ty = cum - w; ty < end; ty++) row[ty] = tok;

    // tail fill: frames beyond total have no token
    const int tail0 = min(total, MAXY);
    for (int ty = tail0 + t; ty < MAXY; ty += TXN) row[ty] = (short)-1;

    // g_sidx complete for this block -> release to dependent kernel
    __syncthreads();
#if __CUDA_ARCH__ >= 900
    cudaTriggerProgrammaticLaunchCompletion();
#endif

    // y_mask, one float4 per thread (not read by expand)
    if (y_mask_out != nullptr) {
        const int v0 = t * 4;
        float4 m;
        m.x = (v0 + 0 < ylen) ? 1.0f : 0.0f;
        m.y = (v0 + 1 < ylen) ? 1.0f : 0.0f;
        m.z = (v0 + 2 < ylen) ? 1.0f : 0.0f;
        m.w = (v0 + 3 < ylen) ? 1.0f : 0.0f;
        reinterpret_cast<float4*>(y_mask_out + b * MAXY)[t] = m;
    }
}

// R8 structure (best measured): one block per (b,c) row, 256 threads,
// 4x float4, all global loads pre-barrier, __expf in compute chain, PDL.
// Only change vs R8: idx map is int16 -> 4x LDG.64 instead of 4x LDG.128.
__global__ void __launch_bounds__(256)
expand_kernel(const float* __restrict__ m_p,
              const float* __restrict__ logs_p,
              const float* __restrict__ noise,
              float* __restrict__ z) {
    __shared__ float sm[TXN];
    __shared__ float ss[TXN];

    const int bc  = blockIdx.x;      // 0..BB*CC-1
    const int b   = bc / CC;
    const int tid = threadIdx.x;

    const float4* __restrict__ nz4 = reinterpret_cast<const float4*>(noise) + (size_t)bc * (MAXY / 4);
    float4*       __restrict__ z4  = reinterpret_cast<float4*>(z)           + (size_t)bc * (MAXY / 4);
    const uint2*  __restrict__ ix2 = reinterpret_cast<const uint2*>(g_sidx + (size_t)b * MAXY);
    const float4* __restrict__ m4  = reinterpret_cast<const float4*>(m_p    + (size_t)bc * TXN);
    const float4* __restrict__ s4  = reinterpret_cast<const float4*>(logs_p + (size_t)bc * TXN);

    // ---- independent loads: overlap build_map under PDL ----
    float4 mv = m4[tid];
    float4 sv = s4[tid];

    float4 n[4];
    #pragma unroll
    for (int j = 0; j < 4; j++) n[j] = __ldcs(&nz4[tid + j * 256]);

    // ---- wait for g_sidx, then the dependent loads ----
#if __CUDA_ARCH__ >= 900
    cudaGridDependencySynchronize();
#endif
    uint2 ix[4];
    #pragma unroll
    for (int j = 0; j < 4; j++) ix[j] = ix2[tid + j * 256];

    reinterpret_cast<float4*>(sm)[tid] = mv;
    reinterpret_cast<float4*>(ss)[tid] = sv;
    __syncthreads();

    // ---- compute: LDS gathers (broadcast-friendly), MUFU exp, FMA ----
    #pragma unroll
    for (int j = 0; j < 4; j++) {
        const int tt[4] = { (int)(short)(ix[j].x & 0xffffu),
                            (int)(short)(ix[j].x >> 16),
                            (int)(short)(ix[j].y & 0xffffu),
                            (int)(short)(ix[j].y >> 16) };
        const float nv[4] = {n[j].x, n[j].y, n[j].z, n[j].w};
        float ov[4];
        #pragma unroll
        for (int k = 0; k < 4; k++) {
            const int t = tt[k];
            ov[k] = (t >= 0) ? fmaf(nv[k], __expf(ss[t]), sm[t]) : nv[k];
        }
        __stcs(&z4[tid + j * 256], make_float4(ov[0], ov[1], ov[2], ov[3]));
    }
}

extern "C" void kernel_launch(void* const* d_in, const int* in_sizes, int n_in,
                              void* d_out, int out_size) {
    const float* m_p    = (const float*)d_in[0];
    const float* logs_p = (const float*)d_in[1];
    const float* logw   = (const float*)d_in[2];
    const float* noise  = (const float*)d_in[3];
    const int*   xlens  = (const int*)d_in[4];

    float* out = (float*)d_out;
    const int zsize = BB * CC * MAXY;            // 12,582,912
    float* z = out;
    float* y_mask = (out_size >= zsize + BB * MAXY) ? (out + zsize) : nullptr;

    build_map_kernel<<<BB, TXN>>>(logw, xlens, y_mask);

    // expand with programmatic dependent launch: independent loads overlap
    // build_map; cudaGridDependencySynchronize() guards the g_sidx reads.
    cudaLaunchConfig_t cfg = {};
    cfg.gridDim  = dim3(BB * CC);
    cfg.blockDim = dim3(256);
    cfg.dynamicSmemBytes = 0;
    cfg.stream = 0;
    cudaLaunchAttribute attr[1];
    attr[0].id = cudaLaunchAttributeProgrammaticStreamSerialization;
    attr[0].val.programmaticStreamSerializationAllowed = 1;
    cfg.attrs = attr;
    cfg.numAttrs = 1;
    cudaLaunchKernelEx(&cfg, expand_kernel, m_p, logs_p, noise, z);
}